// round 6
// baseline (speedup 1.0000x reference)
#include <cuda_runtime.h>

// GraphVampNet EGNN, sm_103a. Round 6: lane-per-edge, warp-uniform broadcast
// weight loads, packed f32x2 FFMA2 GEMVs.
// B=512 frames, N=128 nodes, K=16 neighbors (j=(i+d)&127), H=16, NL=4, NC=6.
// CTA = 256 threads = 128 nodes x 2 lanes; lane e handles edges d=1+8e..8+8e
// and computes ALL 16 outputs of each edge-MLP stage in registers.

#define B_  512
#define N_  128
#define K_  16
#define H_  16
#define NC_ 6
#define NL_ 4

#define SZ_E1 (34*16)
#define SZ_E2 (16*16)
#define SZ_N1 (32*16)
#define SZ_N2 (16*16)
#define SZ_C1 (16*16)
#define SZ_C2 (16)

#define FULL 0xffffffffu
#define HS 20   // node-state row stride (words): 16B-aligned, mild conflicts only

typedef unsigned long long u64;

__device__ __forceinline__ float silu_f(float v) {
    return __fdividef(v, 1.0f + __expf(-v));   // MUFU; rel err ~1e-6
}
__device__ __forceinline__ float4 ld4(const float* p) {
    return *reinterpret_cast<const float4*>(p);
}
// ---- packed f32x2 helpers (sm_103a dual-fp32 pipe; exact fp32 fma) ----
__device__ __forceinline__ u64 pk2(float x, float y) {
    u64 r; asm("mov.b64 %0, {%1, %2};" : "=l"(r) : "f"(x), "f"(y)); return r;
}
__device__ __forceinline__ u64 bc2(float s) {
    u64 r; asm("mov.b64 %0, {%1, %1};" : "=l"(r) : "f"(s)); return r;
}
__device__ __forceinline__ void up2(u64 v, float &x, float &y) {
    asm("mov.b64 {%0, %1}, %2;" : "=f"(x), "=f"(y) : "l"(v));
}
__device__ __forceinline__ void ff2(u64 &acc, float wx, float wy, u64 s2) {
    asm("fma.rn.f32x2 %0, %1, %2, %0;" : "+l"(acc) : "l"(pk2(wx, wy)), "l"(s2));
}

// acc(8 f32x2 pairs = 16 outs) += in[k] * W[k*16 + 0..15], k = 0..15
__device__ __forceinline__ void gemv16(u64 (&acc)[8], const float (&in)[16], const float* W) {
    #pragma unroll
    for (int k = 0; k < 16; ++k) {
        const u64 s2 = bc2(in[k]);
        float4 w0 = ld4(W + k*16),     w1 = ld4(W + k*16 + 4);
        float4 w2 = ld4(W + k*16 + 8), w3 = ld4(W + k*16 + 12);
        ff2(acc[0], w0.x, w0.y, s2); ff2(acc[1], w0.z, w0.w, s2);
        ff2(acc[2], w1.x, w1.y, s2); ff2(acc[3], w1.z, w1.w, s2);
        ff2(acc[4], w2.x, w2.y, s2); ff2(acc[5], w2.z, w2.w, s2);
        ff2(acc[6], w3.x, w3.y, s2); ff2(acc[7], w3.z, w3.w, s2);
    }
}
// half-width (8 outputs): W must be pre-offset to the owned column slice
__device__ __forceinline__ void gemv8(u64 (&acc)[4], const float (&in)[16], const float* W) {
    #pragma unroll
    for (int k = 0; k < 16; ++k) {
        const u64 s2 = bc2(in[k]);
        float4 w0 = ld4(W + k*16), w1 = ld4(W + k*16 + 4);
        ff2(acc[0], w0.x, w0.y, s2); ff2(acc[1], w0.z, w0.w, s2);
        ff2(acc[2], w1.x, w1.y, s2); ff2(acc[3], w1.z, w1.w, s2);
    }
}
__device__ __forceinline__ void bias8(u64 (&acc)[8], const float* B) {
    float4 b0 = ld4(B), b1 = ld4(B+4), b2 = ld4(B+8), b3 = ld4(B+12);
    acc[0]=pk2(b0.x,b0.y); acc[1]=pk2(b0.z,b0.w);
    acc[2]=pk2(b1.x,b1.y); acc[3]=pk2(b1.z,b1.w);
    acc[4]=pk2(b2.x,b2.y); acc[5]=pk2(b2.z,b2.w);
    acc[6]=pk2(b3.x,b3.y); acc[7]=pk2(b3.z,b3.w);
}
__device__ __forceinline__ void bias4(u64 (&acc)[4], const float* B) {
    float4 b0 = ld4(B), b1 = ld4(B+4);
    acc[0]=pk2(b0.x,b0.y); acc[1]=pk2(b0.z,b0.w);
    acc[2]=pk2(b1.x,b1.y); acc[3]=pk2(b1.z,b1.w);
}
__device__ __forceinline__ void unp16(const u64 (&a)[8], float (&o)[16]) {
    #pragma unroll
    for (int p = 0; p < 8; ++p) up2(a[p], o[2*p], o[2*p+1]);
}
__device__ __forceinline__ void unp8(const u64 (&a)[4], float (&o)[8]) {
    #pragma unroll
    for (int p = 0; p < 4; ++p) up2(a[p], o[2*p], o[2*p+1]);
}
__device__ __forceinline__ void load16(float (&r)[16], const float* p) {
    float4 v0 = ld4(p), v1 = ld4(p+4), v2 = ld4(p+8), v3 = ld4(p+12);
    r[0]=v0.x; r[1]=v0.y; r[2]=v0.z; r[3]=v0.w;
    r[4]=v1.x; r[5]=v1.y; r[6]=v1.z; r[7]=v1.w;
    r[8]=v2.x; r[9]=v2.y; r[10]=v2.z; r[11]=v2.w;
    r[12]=v3.x; r[13]=v3.y; r[14]=v3.z; r[15]=v3.w;
}

__global__ void __launch_bounds__(2 * N_, 3)
egnn_kernel(const float* __restrict__ data,      // [B, N, 3+N]
            const float* __restrict__ emb_w,     // [N, H]
            const float* __restrict__ ein_w, const float* __restrict__ ein_b,
            const float* __restrict__ eout_w, const float* __restrict__ eout_b,
            const float* __restrict__ fc_w,  const float* __restrict__ fc_b,
            const float* __restrict__ e1_w,  const float* __restrict__ e1_b,
            const float* __restrict__ e2_w,  const float* __restrict__ e2_b,
            const float* __restrict__ n1_w,  const float* __restrict__ n1_b,
            const float* __restrict__ n2_w,  const float* __restrict__ n2_b,
            const float* __restrict__ c1_w,  const float* __restrict__ c1_b,
            const float* __restrict__ c2_w,
            float* __restrict__ out)             // [B, NC]
{
    const int b   = blockIdx.x;
    const int tid = threadIdx.x;
    const int i   = tid >> 1;        // node 0..127
    const int e   = tid & 1;         // half-lane (edge group / output half)
    const int e8  = e * 8;

    __shared__ __align__(16) float s_h[N_][HS];
    __shared__ __align__(16) float s_y[N_][HS];     // e1 neighbor-half per node
    __shared__ __align__(16) float s_pre[N_][HS];   // e1 self-half; reused as exchange buf
    __shared__ __align__(16) float4 s_x4[N_];

    __shared__ __align__(16) float w_e1[NL_ * SZ_E1], w_e2[NL_ * SZ_E2];
    __shared__ __align__(16) float w_n1[NL_ * SZ_N1], w_n2[NL_ * SZ_N2];
    __shared__ __align__(16) float w_c1[NL_ * SZ_C1], w_c2[NL_ * SZ_C2];
    __shared__ __align__(16) float b_e1[NL_ * 16], b_e2[NL_ * 16];
    __shared__ __align__(16) float b_n1[NL_ * 16], b_n2[NL_ * 16], b_c1[NL_ * 16];
    __shared__ __align__(16) float s_ein[16 * 16], sb_ein[16];
    __shared__ __align__(16) float s_eout[16 * 16], sb_eout[16];
    __shared__ float s_fc[16 * NC_], sb_fc[NC_];
    __shared__ float s_pool[H_];

    const int NT = 2 * N_;
    for (int t = tid; t < NL_ * SZ_E1; t += NT) w_e1[t] = e1_w[t];
    for (int t = tid; t < NL_ * SZ_E2; t += NT) w_e2[t] = e2_w[t];
    for (int t = tid; t < NL_ * SZ_N1; t += NT) w_n1[t] = n1_w[t];
    for (int t = tid; t < NL_ * SZ_N2; t += NT) w_n2[t] = n2_w[t];
    for (int t = tid; t < NL_ * SZ_C1; t += NT) w_c1[t] = c1_w[t];
    for (int t = tid; t < NL_ * SZ_C2; t += NT) w_c2[t] = c2_w[t];
    for (int t = tid; t < NL_ * 16; t += NT) {
        b_e1[t] = e1_b[t]; b_e2[t] = e2_b[t];
        b_n1[t] = n1_b[t]; b_n2[t] = n2_b[t]; b_c1[t] = c1_b[t];
    }
    for (int t = tid; t < 16 * 16; t += NT) { s_ein[t] = ein_w[t]; s_eout[t] = eout_w[t]; }
    if (tid < 16) { sb_ein[tid] = ein_b[tid]; sb_eout[tid] = eout_b[tid]; }
    for (int t = tid; t < 16 * NC_; t += NT) s_fc[t] = fc_w[t];
    if (tid < NC_) sb_fc[tid] = fc_b[tid];

    float xi0, xi1, xi2;
    {
        const float* dptr = data + ((size_t)b * N_ + i) * (3 + N_);
        xi0 = dptr[0]; xi1 = dptr[1]; xi2 = dptr[2];
    }
    __syncthreads();

    // ---- init: h = emb @ ein_w + ein_b  (lane pair splits 16 outputs 8/8) ----
    {
        float ef[16];
        const float* er = emb_w + i * H_;
        #pragma unroll
        for (int k = 0; k < 16; ++k) ef[k] = er[k];
        u64 au[4]; bias4(au, sb_ein + e8);
        gemv8(au, ef, s_ein + e8);
        float h0[8]; unp8(au, h0);
        *(float4*)&s_h[i][e8]     = make_float4(h0[0], h0[1], h0[2], h0[3]);
        *(float4*)&s_h[i][e8 + 4] = make_float4(h0[4], h0[5], h0[6], h0[7]);
        if (e == 0) s_x4[i] = make_float4(xi0, xi1, xi2, 0.0f);
    }
    __syncthreads();

    // ---- E_GCL layers ----
    #pragma unroll 1
    for (int l = 0; l < NL_; ++l) {
        const float* We1 = w_e1 + l * SZ_E1;
        const float* We2 = w_e2 + l * SZ_E2;
        const float* Wc1 = w_c1 + l * SZ_C1;
        const float* Wc2 = w_c2 + l * SZ_C2;

        // Phase A (per node, lane pair splits): e==0 -> pre (bias + e_attr row +
        // h_i @ rows 0..15); e==1 -> y_i (h_i @ rows 16..31)
        {
            float hf[16]; load16(hf, &s_h[i][0]);
            if (e == 0) {
                u64 acc[8]; bias8(acc, b_e1 + l * 16);
                {   // + e_attr(=1) row 33
                    const u64 one2 = bc2(1.0f);
                    const float* w = We1 + 33 * 16;
                    float4 w0 = ld4(w), w1 = ld4(w+4), w2 = ld4(w+8), w3 = ld4(w+12);
                    ff2(acc[0], w0.x, w0.y, one2); ff2(acc[1], w0.z, w0.w, one2);
                    ff2(acc[2], w1.x, w1.y, one2); ff2(acc[3], w1.z, w1.w, one2);
                    ff2(acc[4], w2.x, w2.y, one2); ff2(acc[5], w2.z, w2.w, one2);
                    ff2(acc[6], w3.x, w3.y, one2); ff2(acc[7], w3.z, w3.w, one2);
                }
                gemv16(acc, hf, We1);
                float o16[16]; unp16(acc, o16);
                *(float4*)&s_pre[i][0]  = make_float4(o16[0], o16[1], o16[2], o16[3]);
                *(float4*)&s_pre[i][4]  = make_float4(o16[4], o16[5], o16[6], o16[7]);
                *(float4*)&s_pre[i][8]  = make_float4(o16[8], o16[9], o16[10], o16[11]);
                *(float4*)&s_pre[i][12] = make_float4(o16[12], o16[13], o16[14], o16[15]);
            } else {
                u64 acc[8] = {0, 0, 0, 0, 0, 0, 0, 0};
                gemv16(acc, hf, We1 + 16 * 16);
                float o16[16]; unp16(acc, o16);
                *(float4*)&s_y[i][0]  = make_float4(o16[0], o16[1], o16[2], o16[3]);
                *(float4*)&s_y[i][4]  = make_float4(o16[4], o16[5], o16[6], o16[7]);
                *(float4*)&s_y[i][8]  = make_float4(o16[8], o16[9], o16[10], o16[11]);
                *(float4*)&s_y[i][12] = make_float4(o16[12], o16[13], o16[14], o16[15]);
            }
        }
        __syncthreads();

        // Phase B: 8 edges per lane, all 16 outputs per stage in registers
        float accm[16];
        #pragma unroll
        for (int o = 0; o < 16; ++o) accm[o] = 0.0f;
        float ax0 = 0.f, ax1 = 0.f, ax2 = 0.f;

        #pragma unroll 1
        for (int dd = 0; dd < 8; ++dd) {
            const int d = 1 + e8 + dd;
            const int j = (i + d) & (N_ - 1);
            float4 xj = s_x4[j];
            const float dx = xi0 - xj.x, dy = xi1 - xj.y, dz = xi2 - xj.z;
            const float rad = fmaf(dx, dx, fmaf(dy, dy, dz * dz));

            // e1: a = silu(pre_i + y_j + rad * w_row32)
            float a[16];
            #pragma unroll
            for (int c = 0; c < 4; ++c) {
                float4 p4 = ld4(&s_pre[i][4 * c]);
                float4 y4 = ld4(&s_y[j][4 * c]);
                float4 w4 = ld4(We1 + 32 * 16 + 4 * c);
                a[4*c+0] = silu_f(fmaf(rad, w4.x, p4.x + y4.x));
                a[4*c+1] = silu_f(fmaf(rad, w4.y, p4.y + y4.y));
                a[4*c+2] = silu_f(fmaf(rad, w4.z, p4.z + y4.z));
                a[4*c+3] = silu_f(fmaf(rad, w4.w, p4.w + y4.w));
            }
            // e2: m = silu(a @ We2 + b)
            u64 mu[8]; bias8(mu, b_e2 + l * 16);
            gemv16(mu, a, We2);
            float m[16]; unp16(mu, m);
            #pragma unroll
            for (int o = 0; o < 16; ++o) { m[o] = silu_f(m[o]); accm[o] += m[o]; }
            // coord_mlp: t = silu(m @ Wc1 + b) . Wc2
            u64 cu[8]; bias8(cu, b_c1 + l * 16);
            gemv16(cu, m, Wc1);
            float cv[16]; unp16(cu, cv);
            float t = 0.0f;
            #pragma unroll
            for (int c = 0; c < 4; ++c) {
                float4 w = ld4(Wc2 + 4 * c);
                t = fmaf(silu_f(cv[4*c+0]), w.x, t);
                t = fmaf(silu_f(cv[4*c+1]), w.y, t);
                t = fmaf(silu_f(cv[4*c+2]), w.z, t);
                t = fmaf(silu_f(cv[4*c+3]), w.w, t);
            }
            ax0 = fmaf(dx, t, ax0);
            ax1 = fmaf(dy, t, ax1);
            ax2 = fmaf(dz, t, ax2);
        }

        // pair butterfly (lanes 2i <-> 2i+1)
        #pragma unroll
        for (int o = 0; o < 16; ++o) accm[o] += __shfl_xor_sync(FULL, accm[o], 1);
        ax0 += __shfl_xor_sync(FULL, ax0, 1);
        ax1 += __shfl_xor_sync(FULL, ax1, 1);
        ax2 += __shfl_xor_sync(FULL, ax2, 1);
        xi0 = fmaf(ax0, 0.0625f, xi0);   // cnt == 16
        xi1 = fmaf(ax1, 0.0625f, xi1);
        xi2 = fmaf(ax2, 0.0625f, xi2);

        __syncthreads();   // all edge reads of s_x/s_y/s_pre done block-wide

        // Phase C: node_mlp, lane pair splits 16 outputs 8/8; s_pre = exchange
        {
            const float* Wn1 = w_n1 + l * SZ_N1 + e8;
            const float* Wn2 = w_n2 + l * SZ_N2 + e8;
            float hf[16]; load16(hf, &s_h[i][0]);
            u64 nu[4]; bias4(nu, b_n1 + l * 16 + e8);
            gemv8(nu, hf, Wn1);
            gemv8(nu, accm, Wn1 + 16 * 16);
            float na[8]; unp8(nu, na);
            #pragma unroll
            for (int o = 0; o < 8; ++o) na[o] = silu_f(na[o]);
            *(float4*)&s_pre[i][e8]     = make_float4(na[0], na[1], na[2], na[3]);
            *(float4*)&s_pre[i][e8 + 4] = make_float4(na[4], na[5], na[6], na[7]);
            __syncwarp();
            float nf[16]; load16(nf, &s_pre[i][0]);
            u64 hu[4]; bias4(hu, b_n2 + l * 16 + e8);
            gemv8(hu, nf, Wn2);
            float hb[8]; unp8(hu, hb);
            float4 r0 = ld4(&s_h[i][e8]), r1 = ld4(&s_h[i][e8 + 4]);
            hb[0] += r0.x; hb[1] += r0.y; hb[2] += r0.z; hb[3] += r0.w;
            hb[4] += r1.x; hb[5] += r1.y; hb[6] += r1.z; hb[7] += r1.w;
            __syncwarp();   // partner's reads of old s_h row complete
            *(float4*)&s_h[i][e8]     = make_float4(hb[0], hb[1], hb[2], hb[3]);
            *(float4*)&s_h[i][e8 + 4] = make_float4(hb[4], hb[5], hb[6], hb[7]);
            if (e == 0) s_x4[i] = make_float4(xi0, xi1, xi2, 0.0f);
        }
        __syncthreads();
    }

    // ---- embedding_out + pooling ----
    {
        float hf[16]; load16(hf, &s_h[i][0]);
        u64 eu[4]; bias4(eu, sb_eout + e8);
        gemv8(eu, hf, s_eout + e8);
        float ho[8]; unp8(eu, ho);
        __syncthreads();
        *(float4*)&s_h[i][e8]     = make_float4(ho[0], ho[1], ho[2], ho[3]);
        *(float4*)&s_h[i][e8 + 4] = make_float4(ho[4], ho[5], ho[6], ho[7]);
    }
    __syncthreads();

    if (tid < H_) {
        float s = 0.0f;
        for (int j = 0; j < N_; ++j) s += s_h[j][tid];
        s_pool[tid] = s * (1.0f / (float)N_);
    }
    __syncthreads();

    if (tid == 0) {
        float logit[NC_];
        float mx = -1e30f;
        #pragma unroll
        for (int c = 0; c < NC_; ++c) {
            float s = sb_fc[c];
            #pragma unroll
            for (int k = 0; k < H_; ++k) s = fmaf(s_pool[k], s_fc[k * NC_ + c], s);
            logit[c] = s;
            mx = fmaxf(mx, s);
        }
        float den = 0.0f;
        float ev[NC_];
        #pragma unroll
        for (int c = 0; c < NC_; ++c) { ev[c] = expf(logit[c] - mx); den += ev[c]; }
        const float inv = 1.0f / den;
        #pragma unroll
        for (int c = 0; c < NC_; ++c) out[b * NC_ + c] = ev[c] * inv;
    }
}

extern "C" void kernel_launch(void* const* d_in, const int* in_sizes, int n_in,
                              void* d_out, int out_size)
{
    const float* data   = (const float*)d_in[0];
    const float* emb_w  = (const float*)d_in[3];
    const float* ein_w  = (const float*)d_in[4];
    const float* ein_b  = (const float*)d_in[5];
    const float* eout_w = (const float*)d_in[6];
    const float* eout_b = (const float*)d_in[7];
    const float* fc_w   = (const float*)d_in[8];
    const float* fc_b   = (const float*)d_in[9];
    const float* e1_w   = (const float*)d_in[10];
    const float* e1_b   = (const float*)d_in[11];
    const float* e2_w   = (const float*)d_in[12];
    const float* e2_b   = (const float*)d_in[13];
    const float* n1_w   = (const float*)d_in[14];
    const float* n1_b   = (const float*)d_in[15];
    const float* n2_w   = (const float*)d_in[16];
    const float* n2_b   = (const float*)d_in[17];
    const float* c1_w   = (const float*)d_in[18];
    const float* c1_b   = (const float*)d_in[19];
    const float* c2_w   = (const float*)d_in[20];
    float* out = (float*)d_out;

    egnn_kernel<<<B_, 2 * N_>>>(data, emb_w, ein_w, ein_b, eout_w, eout_b,
                                fc_w, fc_b, e1_w, e1_b, e2_w, e2_b,
                                n1_w, n1_b, n2_w, n2_b, c1_w, c1_b, c2_w, out);
}

// round 7
// speedup vs baseline: 7.3790x; 7.3790x over previous
#include <cuda_runtime.h>

// GraphVampNet EGNN, sm_103a. Round 7: pair-split (2 lanes/node, 8 outputs
// each), 2-edge pairing, two-pointer partner-half GEMVs (8 shfl_xor per
// edge-stage instead of 16 broadcast SHFLs). MIO(L1)-bound kernel.
// B=512 frames, N=128 nodes, K=16 neighbors (j=(i+d)&127), H=16, NL=4, NC=6.

#define B_  512
#define N_  128
#define K_  16
#define H_  16
#define NC_ 6
#define NL_ 4

#define SZ_E1 (34*16)
#define SZ_E2 (16*16)
#define SZ_N1 (32*16)
#define SZ_N2 (16*16)
#define SZ_C1 (16*16)
#define SZ_C2 (16)

#define FULL 0xffffffffu
#define HS 20   // node-state row stride (words): 16B-aligned

__device__ __forceinline__ float silu_f(float v) {
    return __fdividef(v, 1.0f + __expf(-v));   // MUFU; rel err ~1e-6
}
__device__ __forceinline__ float4 ld4(const float* p) {
    return *reinterpret_cast<const float4*>(p);
}
// acc[0..7] += s * w[0..7]  (2x LDS.128 + 8 FMA)
__device__ __forceinline__ void fma8(float (&acc)[8], float s, const float* w) {
    float4 w0 = ld4(w), w1 = ld4(w + 4);
    acc[0] = fmaf(s, w0.x, acc[0]); acc[1] = fmaf(s, w0.y, acc[1]);
    acc[2] = fmaf(s, w0.z, acc[2]); acc[3] = fmaf(s, w0.w, acc[3]);
    acc[4] = fmaf(s, w1.x, acc[4]); acc[5] = fmaf(s, w1.y, acc[5]);
    acc[6] = fmaf(s, w1.z, acc[6]); acc[7] = fmaf(s, w1.w, acc[7]);
}
// two edges share one weight-row load
__device__ __forceinline__ void fma8x2(float (&A)[8], float (&B)[8],
                                       float sa, float sb, const float* w) {
    float4 w0 = ld4(w), w1 = ld4(w + 4);
    A[0] = fmaf(sa, w0.x, A[0]); B[0] = fmaf(sb, w0.x, B[0]);
    A[1] = fmaf(sa, w0.y, A[1]); B[1] = fmaf(sb, w0.y, B[1]);
    A[2] = fmaf(sa, w0.z, A[2]); B[2] = fmaf(sb, w0.z, B[2]);
    A[3] = fmaf(sa, w0.w, A[3]); B[3] = fmaf(sb, w0.w, B[3]);
    A[4] = fmaf(sa, w1.x, A[4]); B[4] = fmaf(sb, w1.x, B[4]);
    A[5] = fmaf(sa, w1.y, A[5]); B[5] = fmaf(sb, w1.y, B[5]);
    A[6] = fmaf(sa, w1.z, A[6]); B[6] = fmaf(sb, w1.z, B[6]);
    A[7] = fmaf(sa, w1.w, A[7]); B[7] = fmaf(sb, w1.w, B[7]);
}
__device__ __forceinline__ void bias8(float (&acc)[8], const float* p) {
    float4 b0 = ld4(p), b1 = ld4(p + 4);
    acc[0] = b0.x; acc[1] = b0.y; acc[2] = b0.z; acc[3] = b0.w;
    acc[4] = b1.x; acc[5] = b1.y; acc[6] = b1.z; acc[7] = b1.w;
}
__device__ __forceinline__ void load16(float (&r)[16], const float* p) {
    float4 v0 = ld4(p), v1 = ld4(p+4), v2 = ld4(p+8), v3 = ld4(p+12);
    r[0]=v0.x; r[1]=v0.y; r[2]=v0.z; r[3]=v0.w;
    r[4]=v1.x; r[5]=v1.y; r[6]=v1.z; r[7]=v1.w;
    r[8]=v2.x; r[9]=v2.y; r[10]=v2.z; r[11]=v2.w;
    r[12]=v3.x; r[13]=v3.y; r[14]=v3.z; r[15]=v3.w;
}
__device__ __forceinline__ void st8(float* p, const float (&a)[8]) {
    *reinterpret_cast<float4*>(p)     = make_float4(a[0], a[1], a[2], a[3]);
    *reinterpret_cast<float4*>(p + 4) = make_float4(a[4], a[5], a[6], a[7]);
}

__global__ void __launch_bounds__(2 * N_, 3)
egnn_kernel(const float* __restrict__ data,      // [B, N, 3+N]
            const float* __restrict__ emb_w,     // [N, H]
            const float* __restrict__ ein_w, const float* __restrict__ ein_b,
            const float* __restrict__ eout_w, const float* __restrict__ eout_b,
            const float* __restrict__ fc_w,  const float* __restrict__ fc_b,
            const float* __restrict__ e1_w,  const float* __restrict__ e1_b,
            const float* __restrict__ e2_w,  const float* __restrict__ e2_b,
            const float* __restrict__ n1_w,  const float* __restrict__ n1_b,
            const float* __restrict__ n2_w,  const float* __restrict__ n2_b,
            const float* __restrict__ c1_w,  const float* __restrict__ c1_b,
            const float* __restrict__ c2_w,
            float* __restrict__ out)             // [B, NC]
{
    const int b   = blockIdx.x;
    const int tid = threadIdx.x;
    const int i   = tid >> 1;        // node 0..127
    const int e   = tid & 1;         // lane within pair
    const int co  = e * 8;           // owned output-column slice base

    __shared__ __align__(16) float s_h[N_][HS];   // pair-private node features
    __shared__ __align__(16) float s_y[N_][HS];   // e1 neighbor-half (shared)
    __shared__ __align__(16) float4 s_x4[N_];     // coords (shared)

    __shared__ __align__(16) float w_e1[NL_ * SZ_E1], w_e2[NL_ * SZ_E2];
    __shared__ __align__(16) float w_n1[NL_ * SZ_N1], w_n2[NL_ * SZ_N2];
    __shared__ __align__(16) float w_c1[NL_ * SZ_C1], w_c2[NL_ * SZ_C2];
    __shared__ __align__(16) float b_e1[NL_ * 16], b_e2[NL_ * 16];
    __shared__ __align__(16) float b_n1[NL_ * 16], b_n2[NL_ * 16], b_c1[NL_ * 16];
    __shared__ __align__(16) float s_ein[16 * 16], sb_ein[16];
    __shared__ __align__(16) float s_eout[16 * 16], sb_eout[16];
    __shared__ float s_fc[16 * NC_], sb_fc[NC_];
    __shared__ float s_pool[H_];

    const int NT = 2 * N_;
    for (int t = tid; t < NL_ * SZ_E1; t += NT) w_e1[t] = e1_w[t];
    for (int t = tid; t < NL_ * SZ_E2; t += NT) w_e2[t] = e2_w[t];
    for (int t = tid; t < NL_ * SZ_N1; t += NT) w_n1[t] = n1_w[t];
    for (int t = tid; t < NL_ * SZ_N2; t += NT) w_n2[t] = n2_w[t];
    for (int t = tid; t < NL_ * SZ_C1; t += NT) w_c1[t] = c1_w[t];
    for (int t = tid; t < NL_ * SZ_C2; t += NT) w_c2[t] = c2_w[t];
    for (int t = tid; t < NL_ * 16; t += NT) {
        b_e1[t] = e1_b[t]; b_e2[t] = e2_b[t];
        b_n1[t] = n1_b[t]; b_n2[t] = n2_b[t]; b_c1[t] = c1_b[t];
    }
    for (int t = tid; t < 16 * 16; t += NT) { s_ein[t] = ein_w[t]; s_eout[t] = eout_w[t]; }
    if (tid < 16) { sb_ein[tid] = ein_b[tid]; sb_eout[tid] = eout_b[tid]; }
    for (int t = tid; t < 16 * NC_; t += NT) s_fc[t] = fc_w[t];
    if (tid < NC_) sb_fc[tid] = fc_b[tid];

    float xi0, xi1, xi2;
    {
        const float* dptr = data + ((size_t)b * N_ + i) * (3 + N_);
        xi0 = dptr[0]; xi1 = dptr[1]; xi2 = dptr[2];
    }
    __syncthreads();

    // ---- init: h = emb @ ein_w + ein_b  (pair splits 16 outputs 8/8) ----
    {
        float acc[8];
        bias8(acc, sb_ein + co);
        const float* er = emb_w + i * H_;
        #pragma unroll
        for (int k = 0; k < 16; ++k) fma8(acc, er[k], s_ein + k * 16 + co);
        st8(&s_h[i][co], acc);
        if (e == 0) s_x4[i] = make_float4(xi0, xi1, xi2, 0.0f);
    }
    __syncthreads();

    // ---- E_GCL layers ----
    #pragma unroll 1
    for (int l = 0; l < NL_; ++l) {
        const float* We1c = w_e1 + l * SZ_E1 + co;   // col-sliced e1 weights
        const float* Be2  = b_e2 + l * 16 + co;
        const float* Bc1  = b_c1 + l * 16 + co;
        // two-pointer row bases (own rows / partner rows), col-sliced
        const float* E2o = w_e2 + l * SZ_E2 + co * 16       + co;
        const float* E2x = w_e2 + l * SZ_E2 + (8 - co) * 16 + co;
        const float* C1o = w_c1 + l * SZ_C1 + co * 16       + co;
        const float* C1x = w_c1 + l * SZ_C1 + (8 - co) * 16 + co;

        // Phase A (per node): pre = bias + e_attr row + h_i @ rows0-15 (own cols);
        //                     y_i = h_i @ rows16-31 (own cols) -> s_y
        float pre[8];
        {
            float hf[16]; load16(hf, &s_h[i][0]);
            bias8(pre, b_e1 + l * 16 + co);
            fma8(pre, 1.0f, We1c + 33 * 16);
            float yq[8] = {0,0,0,0,0,0,0,0};
            #pragma unroll
            for (int k = 0; k < 16; ++k) {
                fma8(pre, hf[k], We1c + k * 16);
                fma8(yq,  hf[k], We1c + (16 + k) * 16);
            }
            st8(&s_y[i][co], yq);
        }
        __syncthreads();   // s_y + s_x (from prev layer) visible

        float accm[8] = {0,0,0,0,0,0,0,0};
        float ax0 = 0.f, ax1 = 0.f, ax2 = 0.f;

        #pragma unroll 1
        for (int it = 0; it < 8; ++it) {
            const int d  = 1 + 2 * it;
            const int j0 = (i + d)     & (N_ - 1);
            const int j1 = (i + d + 1) & (N_ - 1);
            float4 xj0 = s_x4[j0];
            float4 xj1 = s_x4[j1];
            const float d00 = xi0-xj0.x, d01 = xi1-xj0.y, d02 = xi2-xj0.z;
            const float d10 = xi0-xj1.x, d11 = xi1-xj1.y, d12 = xi2-xj1.z;
            const float rad0 = fmaf(d00,d00, fmaf(d01,d01, d02*d02));
            const float rad1 = fmaf(d10,d10, fmaf(d11,d11, d12*d12));

            // e1: a = silu(pre + y_j + rad * w_row32)   (own 8 cols)
            float a0[8], a1[8];
            {
                float4 w0 = ld4(We1c + 32*16), w1 = ld4(We1c + 32*16 + 4);
                float4 ya = ld4(&s_y[j0][co]), yb = ld4(&s_y[j0][co+4]);
                float4 za = ld4(&s_y[j1][co]), zb = ld4(&s_y[j1][co+4]);
                a0[0]=silu_f(fmaf(rad0,w0.x, pre[0]+ya.x));
                a0[1]=silu_f(fmaf(rad0,w0.y, pre[1]+ya.y));
                a0[2]=silu_f(fmaf(rad0,w0.z, pre[2]+ya.z));
                a0[3]=silu_f(fmaf(rad0,w0.w, pre[3]+ya.w));
                a0[4]=silu_f(fmaf(rad0,w1.x, pre[4]+yb.x));
                a0[5]=silu_f(fmaf(rad0,w1.y, pre[5]+yb.y));
                a0[6]=silu_f(fmaf(rad0,w1.z, pre[6]+yb.z));
                a0[7]=silu_f(fmaf(rad0,w1.w, pre[7]+yb.w));
                a1[0]=silu_f(fmaf(rad1,w0.x, pre[0]+za.x));
                a1[1]=silu_f(fmaf(rad1,w0.y, pre[1]+za.y));
                a1[2]=silu_f(fmaf(rad1,w0.z, pre[2]+za.z));
                a1[3]=silu_f(fmaf(rad1,w0.w, pre[3]+za.w));
                a1[4]=silu_f(fmaf(rad1,w1.x, pre[4]+zb.x));
                a1[5]=silu_f(fmaf(rad1,w1.y, pre[5]+zb.y));
                a1[6]=silu_f(fmaf(rad1,w1.z, pre[6]+zb.z));
                a1[7]=silu_f(fmaf(rad1,w1.w, pre[7]+zb.w));
            }

            // e2: m = silu(a_full @ We2 + b). Own-half rows from regs,
            // partner-half rows via shfl_xor + offset row base.
            float m0[8], m1[8];
            bias8(m0, Be2);
            #pragma unroll
            for (int o = 0; o < 8; ++o) m1[o] = m0[o];
            #pragma unroll
            for (int r = 0; r < 8; ++r) fma8x2(m0, m1, a0[r], a1[r], E2o + r * 16);
            #pragma unroll
            for (int r = 0; r < 8; ++r) {
                const float s0 = __shfl_xor_sync(FULL, a0[r], 1);
                const float s1 = __shfl_xor_sync(FULL, a1[r], 1);
                fma8x2(m0, m1, s0, s1, E2x + r * 16);
            }
            #pragma unroll
            for (int o = 0; o < 8; ++o) {
                m0[o] = silu_f(m0[o]); m1[o] = silu_f(m1[o]);
                accm[o] += m0[o] + m1[o];
            }

            // coord_mlp: t = silu(m_full @ Wc1 + b) . Wc2 (reuse a as accum)
            bias8(a0, Bc1);
            #pragma unroll
            for (int o = 0; o < 8; ++o) a1[o] = a0[o];
            #pragma unroll
            for (int r = 0; r < 8; ++r) fma8x2(a0, a1, m0[r], m1[r], C1o + r * 16);
            #pragma unroll
            for (int r = 0; r < 8; ++r) {
                const float s0 = __shfl_xor_sync(FULL, m0[r], 1);
                const float s1 = __shfl_xor_sync(FULL, m1[r], 1);
                fma8x2(a0, a1, s0, s1, C1x + r * 16);
            }
            float t0, t1;
            {
                float4 w0 = ld4(w_c2 + l * SZ_C2 + co);
                float4 w1 = ld4(w_c2 + l * SZ_C2 + co + 4);
                t0 = silu_f(a0[0]) * w0.x;
                t0 = fmaf(silu_f(a0[1]), w0.y, t0);
                t0 = fmaf(silu_f(a0[2]), w0.z, t0);
                t0 = fmaf(silu_f(a0[3]), w0.w, t0);
                t0 = fmaf(silu_f(a0[4]), w1.x, t0);
                t0 = fmaf(silu_f(a0[5]), w1.y, t0);
                t0 = fmaf(silu_f(a0[6]), w1.z, t0);
                t0 = fmaf(silu_f(a0[7]), w1.w, t0);
                t1 = silu_f(a1[0]) * w0.x;
                t1 = fmaf(silu_f(a1[1]), w0.y, t1);
                t1 = fmaf(silu_f(a1[2]), w0.z, t1);
                t1 = fmaf(silu_f(a1[3]), w0.w, t1);
                t1 = fmaf(silu_f(a1[4]), w1.x, t1);
                t1 = fmaf(silu_f(a1[5]), w1.y, t1);
                t1 = fmaf(silu_f(a1[6]), w1.z, t1);
                t1 = fmaf(silu_f(a1[7]), w1.w, t1);
            }
            t0 += __shfl_xor_sync(FULL, t0, 1);   // partner holds other 8 dims
            t1 += __shfl_xor_sync(FULL, t1, 1);

            ax0 = fmaf(d00, t0, fmaf(d10, t1, ax0));
            ax1 = fmaf(d01, t0, fmaf(d11, t1, ax1));
            ax2 = fmaf(d02, t0, fmaf(d12, t1, ax2));
        }

        xi0 = fmaf(ax0, 0.0625f, xi0);   // cnt == 16
        xi1 = fmaf(ax1, 0.0625f, xi1);
        xi2 = fmaf(ax2, 0.0625f, xi2);

        __syncthreads();   // all Phase-B reads of s_y / s_x done block-wide

        // Phase C: node_mlp (pair-split 8/8); accm/na exchanged via shfl_xor.
        {
            const float* Wn1c = w_n1 + l * SZ_N1 + co;
            const float* N1o = w_n1 + l * SZ_N1 + (16 + co) * 16     + co;
            const float* N1x = w_n1 + l * SZ_N1 + (16 + 8 - co) * 16 + co;
            const float* N2o = w_n2 + l * SZ_N2 + co * 16       + co;
            const float* N2x = w_n2 + l * SZ_N2 + (8 - co) * 16 + co;

            float hf[16]; load16(hf, &s_h[i][0]);   // old h (pair-private row)
            float na[8];
            bias8(na, b_n1 + l * 16 + co);
            #pragma unroll
            for (int k = 0; k < 16; ++k) fma8(na, hf[k], Wn1c + k * 16);
            #pragma unroll
            for (int r = 0; r < 8; ++r) fma8(na, accm[r], N1o + r * 16);
            #pragma unroll
            for (int r = 0; r < 8; ++r)
                fma8(na, __shfl_xor_sync(FULL, accm[r], 1), N1x + r * 16);
            #pragma unroll
            for (int o = 0; o < 8; ++o) na[o] = silu_f(na[o]);

            float hb[8];
            bias8(hb, b_n2 + l * 16 + co);
            #pragma unroll
            for (int r = 0; r < 8; ++r) fma8(hb, na[r], N2o + r * 16);
            #pragma unroll
            for (int r = 0; r < 8; ++r)
                fma8(hb, __shfl_xor_sync(FULL, na[r], 1), N2x + r * 16);
            #pragma unroll
            for (int o = 0; o < 8; ++o) hb[o] += hf[co + o];   // residual (regs)

            __syncwarp();          // partner's load16 of old s_h row complete
            st8(&s_h[i][co], hb);
            if (e == 0) s_x4[i] = make_float4(xi0, xi1, xi2, 0.0f);
            // next Phase A reads s_h (pair-private, syncwarp'd) and the
            // A->B __syncthreads orders s_x4 for neighbors.
        }
        __syncwarp();
    }

    // ---- embedding_out + pooling ----
    {
        float hf[16]; load16(hf, &s_h[i][0]);
        float ho[8];
        bias8(ho, sb_eout + co);
        #pragma unroll
        for (int k = 0; k < 16; ++k) fma8(ho, hf[k], s_eout + k * 16 + co);
        __syncthreads();
        st8(&s_h[i][co], ho);
    }
    __syncthreads();

    if (tid < H_) {
        float s = 0.0f;
        for (int j = 0; j < N_; ++j) s += s_h[j][tid];
        s_pool[tid] = s * (1.0f / (float)N_);
    }
    __syncthreads();

    if (tid == 0) {
        float logit[NC_];
        float mx = -1e30f;
        #pragma unroll
        for (int c = 0; c < NC_; ++c) {
            float s = sb_fc[c];
            #pragma unroll
            for (int k = 0; k < H_; ++k) s = fmaf(s_pool[k], s_fc[k * NC_ + c], s);
            logit[c] = s;
            mx = fmaxf(mx, s);
        }
        float den = 0.0f;
        float ev[NC_];
        #pragma unroll
        for (int c = 0; c < NC_; ++c) { ev[c] = expf(logit[c] - mx); den += ev[c]; }
        const float inv = 1.0f / den;
        #pragma unroll
        for (int c = 0; c < NC_; ++c) out[b * NC_ + c] = ev[c] * inv;
    }
}

extern "C" void kernel_launch(void* const* d_in, const int* in_sizes, int n_in,
                              void* d_out, int out_size)
{
    const float* data   = (const float*)d_in[0];
    const float* emb_w  = (const float*)d_in[3];
    const float* ein_w  = (const float*)d_in[4];
    const float* ein_b  = (const float*)d_in[5];
    const float* eout_w = (const float*)d_in[6];
    const float* eout_b = (const float*)d_in[7];
    const float* fc_w   = (const float*)d_in[8];
    const float* fc_b   = (const float*)d_in[9];
    const float* e1_w   = (const float*)d_in[10];
    const float* e1_b   = (const float*)d_in[11];
    const float* e2_w   = (const float*)d_in[12];
    const float* e2_b   = (const float*)d_in[13];
    const float* n1_w   = (const float*)d_in[14];
    const float* n1_b   = (const float*)d_in[15];
    const float* n2_w   = (const float*)d_in[16];
    const float* n2_b   = (const float*)d_in[17];
    const float* c1_w   = (const float*)d_in[18];
    const float* c1_b   = (const float*)d_in[19];
    const float* c2_w   = (const float*)d_in[20];
    float* out = (float*)d_out;

    egnn_kernel<<<B_, 2 * N_>>>(data, emb_w, ein_w, ein_b, eout_w, eout_b,
                                fc_w, fc_b, e1_w, e1_b, e2_w, e2_b,
                                n1_w, n1_b, n2_w, n2_b, c1_w, c1_b, c2_w, out);
}